// round 17
// baseline (speedup 1.0000x reference)
#include <cuda_runtime.h>
#include <math_constants.h>
#include <cstdint>

// ChamferDistanceLoss, B=8, N=4096, D=3 — fused both directions.
// d(i,j) = rn_i + cn_j - 2 p1_i.p2_j computed ONCE per pair.
// Main: block = (batch, 256-row tile, 512-col tile) = 1024 blocks, 128 thr.
//   launch_bounds(128,7): 7 resident/SM -> entire grid in ONE wave (no
//   low-occupancy straggler tail). Each warp: 128-col slice, all 256 rows
//   (8/lane), XOR col rotation (1 shfl per 256 pairs). Row partials combined
//   across warps in smem (multiplicity 8); col partials multiplicity 16.
// Reduce: 320 blocks (256 row-side, 64 col-side LDG.128) + ticket final.

#define NPTS 4096
#define BATCH 8
#define RPB 256
#define CPB 512
#define RT 16
#define CT 8
#define MAIN_BLOCKS (BATCH * RT * CT)       // 1024
#define THREADS 128
#define NWARPS 4
#define WCOLS (CPB / NWARPS)                // 128
#define RED_BLOCKS 320                      // 256 row-side + 64 col-side
#define RED_THREADS 128

__device__ float g_rowpart[MAIN_BLOCKS * RPB];   // 1 MB
__device__ float g_colpart[MAIN_BLOCKS * CPB];   // 2 MB
__device__ float g_sum[RED_BLOCKS];
__device__ unsigned int g_ticket;                // zero-init; reset each call

// ---------------------------------------------------------------------------
__global__ void __launch_bounds__(THREADS, 7)
chamfer_main(const float* __restrict__ p1, const float* __restrict__ p2) {
    __shared__ float4 sc[CPB];                    // (-2x,-2y,-2z,|c|^2)  8 KB
    __shared__ float  s_row[NWARPS * RPB];        // 4 KB

    int bx = blockIdx.x;
    int b  = bx >> 7;                             // batch
    int rt = (bx >> 3) & 15;                      // row tile (256 rows)
    int ct = bx & 7;                              // col tile (512 cols)
    const float* __restrict__ rows = p1 + (b * NPTS + rt * RPB) * 3;
    const float* __restrict__ cols = p2 + (b * NPTS + ct * CPB) * 3;

    int t = threadIdx.x, w = t >> 5, lane = t & 31;

    // Stage 512 candidates: 4 per thread via 3x LDG.128 (48B per thread).
    {
        const float4* s4 = (const float4*)cols + 3 * t;
        float4 v0 = s4[0], v1 = s4[1], v2 = s4[2];
        float cx[4] = { v0.x, v0.w, v1.z, v2.y };
        float cy[4] = { v0.y, v1.x, v1.w, v2.z };
        float cz[4] = { v0.z, v1.y, v2.x, v2.w };
        #pragma unroll
        for (int k = 0; k < 4; ++k) {
            float x = cx[k], y = cy[k], z = cz[k];
            float n = fmaf(x, x, fmaf(y, y, z * z));
            sc[4 * t + k] = make_float4(-2.0f * x, -2.0f * y, -2.0f * z, n);
        }
    }

    // 8 rows per lane (whole 256-row tile per warp).
    float rx[8], ry[8], rz[8], rn[8], rm[8];
    #pragma unroll
    for (int k = 0; k < 8; ++k) {
        int r = k * 32 + lane;
        rx[k] = rows[3 * r + 0];
        ry[k] = rows[3 * r + 1];
        rz[k] = rows[3 * r + 2];
        rn[k] = fmaf(rx[k], rx[k], fmaf(ry[k], ry[k], rz[k] * rz[k]));
        rm[k] = CUDART_INF_F;                     // accumulates e = cn - 2dot
    }
    __syncthreads();

    const char* sbase = (const char*)sc;
    #pragma unroll
    for (int cc = 0; cc < WCOLS / 32; ++cc) {     // 4 groups of 32 cols
        uint32_t off0 = (uint32_t)(w * WCOLS + cc * 32 + lane) * 16u;
        float cm = CUDART_INF_F;
        #pragma unroll 8
        for (int s = 0; s < 32; ++s) {
            float4 c = *(const float4*)(sbase + (off0 ^ ((uint32_t)s << 4)));
            float e[8];
            #pragma unroll
            for (int k = 0; k < 8; ++k) {
                e[k] = fmaf(c.x, rx[k], fmaf(c.y, ry[k], fmaf(c.z, rz[k], c.w)));
                rm[k] = fminf(rm[k], e[k]);       // row side: rn added later
            }
            // col side needs full d = e + rn (rn varies across rows)
            float cv = fminf(
                fminf(fminf(e[0] + rn[0], e[1] + rn[1]),
                      fminf(e[2] + rn[2], e[3] + rn[3])),
                fminf(fminf(e[4] + rn[4], e[5] + rn[5]),
                      fminf(e[6] + rn[6], e[7] + rn[7])));
            cm = fminf(cm, __shfl_xor_sync(0xffffffffu, cv, s));
        }
        // Column (ct*512 + w*128 + cc*32 + lane) reduced over all 256 rows.
        g_colpart[bx * CPB + w * WCOLS + cc * 32 + lane] = cm;
    }

    // Row side: fold rn, then combine across the 4 warps (same rows) in smem.
    #pragma unroll
    for (int k = 0; k < 8; ++k)
        s_row[w * RPB + k * 32 + lane] = rn[k] + rm[k];
    __syncthreads();
    #pragma unroll
    for (int rr = t; rr < RPB; rr += THREADS) {
        float v = fminf(fminf(s_row[rr], s_row[RPB + rr]),
                        fminf(s_row[2 * RPB + rr], s_row[3 * RPB + rr]));
        g_rowpart[bx * RPB + rr] = v;
    }
}

// ---------------------------------------------------------------------------
// Reduce (one launch, ticket-merged final):
//  blocks [0,256):   row side — thread -> one row, min over 8 partials (ct).
//  blocks [256,320): col side — thread -> 4 cols (float4), min over 16 (rt).
//  last block sums the fixed-order g_sum[320] -> loss.
// ---------------------------------------------------------------------------
__global__ void __launch_bounds__(RED_THREADS)
chamfer_reduce(float* __restrict__ out) {
    __shared__ float wsum[RED_THREADS / 32];
    __shared__ bool s_last;
    int bid = blockIdx.x, t = threadIdx.x;

    float s;
    if (bid < 256) {
        int i = bid * RED_THREADS + t;            // 0..32767 row index
        int b = i >> 12;
        int r = i & (NPTS - 1);
        int rt = r >> 8, rr = r & (RPB - 1);
        float rmin = CUDART_INF_F;
        #pragma unroll
        for (int c = 0; c < CT; ++c)
            rmin = fminf(rmin,
                g_rowpart[((b * RT + rt) * CT + c) * RPB + rr]);
        s = rmin;
    } else {
        int q = (bid - 256) * RED_THREADS + t;    // 0..8191 col-quad index
        int b = q >> 10;
        int g4 = q & 1023;
        int ct = g4 >> 7;
        int cc4 = (g4 & 127) * 4;
        float4 acc = make_float4(CUDART_INF_F, CUDART_INF_F,
                                 CUDART_INF_F, CUDART_INF_F);
        #pragma unroll
        for (int rt = 0; rt < RT; ++rt) {
            const float4 v = *(const float4*)
                &g_colpart[((b * RT + rt) * CT + ct) * CPB + cc4];
            acc.x = fminf(acc.x, v.x);
            acc.y = fminf(acc.y, v.y);
            acc.z = fminf(acc.z, v.z);
            acc.w = fminf(acc.w, v.w);
        }
        s = (acc.x + acc.y) + (acc.z + acc.w);
    }

    #pragma unroll
    for (int off = 16; off > 0; off >>= 1)
        s += __shfl_down_sync(0xffffffffu, s, off);
    if ((t & 31) == 0) wsum[t >> 5] = s;
    __syncthreads();
    if (t == 0) {
        float p = 0.0f;
        #pragma unroll
        for (int ww = 0; ww < RED_THREADS / 32; ++ww) p += wsum[ww];
        g_sum[bid] = p;
        __threadfence();
        unsigned int v = atomicAdd(&g_ticket, 1u);
        s_last = (v == RED_BLOCKS - 1);
    }
    __syncthreads();

    // Deterministic final: exactly one block (last to arrive) reduces the
    // fixed-order g_sum array; arithmetic order independent of which block.
    if (s_last) {
        __threadfence();
        float fs = g_sum[t] + g_sum[t + 128] + ((t < 64) ? g_sum[t + 256] : 0.0f);
        #pragma unroll
        for (int off = 16; off > 0; off >>= 1)
            fs += __shfl_down_sync(0xffffffffu, fs, off);
        if ((t & 31) == 0) wsum[t >> 5] = fs;
        __syncthreads();
        if (t == 0) {
            float tot = 0.0f;
            #pragma unroll
            for (int ww = 0; ww < RED_THREADS / 32; ++ww) tot += wsum[ww];
            out[0] = tot * (1.0f / (float)(BATCH * NPTS));
            g_ticket = 0;   // reset for next graph replay
        }
    }
}

extern "C" void kernel_launch(void* const* d_in, const int* in_sizes, int n_in,
                              void* d_out, int out_size) {
    const float* p1 = (const float*)d_in[0];
    const float* p2 = (const float*)d_in[1];
    float* out = (float*)d_out;

    chamfer_main<<<MAIN_BLOCKS, THREADS>>>(p1, p2);
    chamfer_reduce<<<RED_BLOCKS, RED_THREADS>>>(out);
}